// round 2
// baseline (speedup 1.0000x reference)
#include <cuda_runtime.h>

#define BB 64
#define TT 512
#define DD 512
#define HH 512
#define G3 1536
#define NBLK 128

// ---------------- device scratch (no allocations allowed) ----------------
__device__ float g_zi[2][TT][BB][G3];        // [dir][t][b][3H] pre-activations (402 MB)
__device__ float g_h[2][2][BB * HH];         // [ping][dir][b*512+j]
__device__ unsigned g_cnt[512];              // grid barrier counters (zero-init)

// =================================================================
// Kernel 1: zi[d][t][b][g] = x[b][t][:] . w_ih[d][g][:] + b_ih[d][g]
// SGEMM: M=B*T (m = b*512+t), N=1536, K=512. 128x128 tile, 8x8 micro.
// =================================================================
__global__ void __launch_bounds__(256, 2) gemm_zi_kernel(
    const float* __restrict__ x,
    const float* __restrict__ w_fw, const float* __restrict__ b_fw,
    const float* __restrict__ w_bw, const float* __restrict__ b_bw)
{
    const int d = blockIdx.z;
    const float* __restrict__ W  = d ? w_bw : w_fw;
    const float* __restrict__ Bi = d ? b_bw : b_fw;
    float* __restrict__ zi = &g_zi[d][0][0][0];

    __shared__ float As[16][132];
    __shared__ float Bs[16][132];

    const int m0 = blockIdx.y * 128;
    const int n0 = blockIdx.x * 128;
    const int tid = threadIdx.x;
    const int tx = tid & 15;       // n
    const int ty = tid >> 4;       // m

    float acc[8][8];
#pragma unroll
    for (int i = 0; i < 8; i++)
#pragma unroll
        for (int j = 0; j < 8; j++) acc[i][j] = 0.f;

    for (int kt = 0; kt < DD; kt += 16) {
#pragma unroll
        for (int i = 0; i < 2; i++) {
            int l = tid * 2 + i;
            int row = l >> 2, kf = l & 3;
            float4 av = *reinterpret_cast<const float4*>(
                x + (size_t)(m0 + row) * DD + kt + kf * 4);
            As[kf * 4 + 0][row] = av.x; As[kf * 4 + 1][row] = av.y;
            As[kf * 4 + 2][row] = av.z; As[kf * 4 + 3][row] = av.w;
            float4 bv = *reinterpret_cast<const float4*>(
                W + (size_t)(n0 + row) * DD + kt + kf * 4);
            Bs[kf * 4 + 0][row] = bv.x; Bs[kf * 4 + 1][row] = bv.y;
            Bs[kf * 4 + 2][row] = bv.z; Bs[kf * 4 + 3][row] = bv.w;
        }
        __syncthreads();
#pragma unroll
        for (int k = 0; k < 16; k++) {
            float a[8], bb[8];
            *(float4*)&a[0]  = *(const float4*)&As[k][ty * 8];
            *(float4*)&a[4]  = *(const float4*)&As[k][ty * 8 + 4];
            *(float4*)&bb[0] = *(const float4*)&Bs[k][tx * 8];
            *(float4*)&bb[4] = *(const float4*)&Bs[k][tx * 8 + 4];
#pragma unroll
            for (int i = 0; i < 8; i++)
#pragma unroll
                for (int j = 0; j < 8; j++)
                    acc[i][j] += a[i] * bb[j];
        }
        __syncthreads();
    }

    float bias[8];
#pragma unroll
    for (int j = 0; j < 8; j++) bias[j] = Bi[n0 + tx * 8 + j];

#pragma unroll
    for (int i = 0; i < 8; i++) {
        int m = m0 + ty * 8 + i;
        int t = m & (TT - 1);
        int b = m >> 9;
        float* dst = zi + (size_t)(t * BB + b) * G3 + n0 + tx * 8;
        float4 v0, v1;
        v0.x = acc[i][0] + bias[0]; v0.y = acc[i][1] + bias[1];
        v0.z = acc[i][2] + bias[2]; v0.w = acc[i][3] + bias[3];
        v1.x = acc[i][4] + bias[4]; v1.y = acc[i][5] + bias[5];
        v1.z = acc[i][6] + bias[6]; v1.w = acc[i][7] + bias[7];
        *reinterpret_cast<float4*>(dst)     = v0;
        *reinterpret_cast<float4*>(dst + 4) = v1;
    }
}

// =================================================================
// Kernel 2: persistent recurrence. 128 blocks = 2 dirs x 64 j-slices(8).
// W_hh slice (24 rows x 512) lives in SMEM for the whole kernel.
// Per step: stage h (LDG.cg, transpose to SMEM), k-split dot products,
// SMEM partial reduce, fused gates + writes, one grid barrier.
// =================================================================
#define SM_W (512 * 24)
#define SM_H (512 * 68)
#define SM_P (24 * 64 * 4)
#define RNN_SMEM_BYTES ((SM_W + SM_H + SM_P) * 4)

__device__ __forceinline__ void grid_barrier(int idx)
{
    __syncthreads();
    if (threadIdx.x == 0) {
        __threadfence();
        atomicAdd(&g_cnt[idx], 1u);
        unsigned v;
        do {
            v = *((volatile unsigned*)&g_cnt[idx]);
        } while (v != 0u && v < (unsigned)NBLK);   // 0 == already completed+reset
        __threadfence();
    }
    __syncthreads();
}

__global__ void __launch_bounds__(256, 1) rnn_kernel(
    const float* __restrict__ whh_fw, const float* __restrict__ whh_bw,
    const float* __restrict__ bhh_fw, const float* __restrict__ bhh_bw,
    float* __restrict__ out)
{
    extern __shared__ float smem[];
    float* ws = smem;              // [k][24] row-stride 24
    float* hs = ws + SM_W;         // [k][68] (64 batches + pad)
    float* Pm = hs + SM_H;         // [24][64][4] partials

    const int bid = blockIdx.x;
    const int d   = bid >> 6;
    const int j0  = (bid & 63) * 8;
    const float* __restrict__ W  = d ? whh_bw : whh_fw;
    const float* __restrict__ Bh = d ? bhh_bw : bhh_fw;

    const int tid = threadIdx.x;
    const int kq  = tid >> 6;            // 0..3  (k segment of 128)
    const int pos = tid & 63;
    const int bq  = pos & 15;            // 4 batches each
    const int rq  = pos >> 4;            // 6 rows each

    // --- load W_hh slice into SMEM (once, persists all 512 steps) ---
    for (int idx = tid; idx < 24 * 512; idx += 256) {
        int r = idx >> 9, k = idx & 511;
        int grow = ((r >> 3) << 9) + j0 + (r & 7);   // gate*512 + j
        ws[k * 24 + r] = W[(size_t)grow * HH + k];
    }

    // --- pointwise-phase mapping: 2 outputs per thread, same batch ---
    const int o0  = tid * 2;
    const int pb  = o0 >> 3;            // batch
    const int pj0 = o0 & 7;             // j, j+1
    const float bh_r0 = Bh[j0 + pj0],        bh_r1 = Bh[j0 + pj0 + 1];
    const float bh_z0 = Bh[512 + j0 + pj0],  bh_z1 = Bh[512 + j0 + pj0 + 1];
    const float bh_n0 = Bh[1024 + j0 + pj0], bh_n1 = Bh[1024 + j0 + pj0 + 1];

    // --- zero h ping buffer 0 (this block's slice) ---
    for (int idx = tid; idx < 512; idx += 256) {
        int b = idx >> 3, jj = idx & 7;
        g_h[0][d][b * HH + j0 + jj] = 0.f;
    }
    __threadfence();
    grid_barrier(0);

    const size_t HOFF = (size_t)BB * TT * 1024;   // start of h_fw region

    for (int s = 0; s < TT; ++s) {
        const int p = s & 1;
        const int t = d ? (TT - 1 - s) : s;
        const float* __restrict__ hsrc = g_h[p][d];

        // prefetch zi gate pre-activations for this thread's 2 outputs
        const float* __restrict__ zib = &g_zi[d][t][pb][0];
        const float air0 = zib[j0 + pj0],        air1 = zib[j0 + pj0 + 1];
        const float aiz0 = zib[512 + j0 + pj0],  aiz1 = zib[512 + j0 + pj0 + 1];
        const float ain0 = zib[1024 + j0 + pj0], ain1 = zib[1024 + j0 + pj0 + 1];

        // --- stage h into SMEM transposed: hs[k][b] (L2 reads, skip L1) ---
#pragma unroll
        for (int i = 0; i < 32; ++i) {
            int idx = i * 256 + tid;           // float4 index 0..8191
            int b = idx >> 7, kf = idx & 127;
            float4 v = __ldcg(reinterpret_cast<const float4*>(hsrc + b * HH + kf * 4));
            int kb = kf * 4;
            hs[(kb + 0) * 68 + b] = v.x;
            hs[(kb + 1) * 68 + b] = v.y;
            hs[(kb + 2) * 68 + b] = v.z;
            hs[(kb + 3) * 68 + b] = v.w;
        }
        __syncthreads();

        // --- phase A: partial dot products over this thread's k segment ---
        float acc[6][4];
#pragma unroll
        for (int rr = 0; rr < 6; ++rr)
#pragma unroll
            for (int bi = 0; bi < 4; ++bi) acc[rr][bi] = 0.f;

        const float* hp = hs + (kq * 128) * 68 + bq * 4;
        const float* wp = ws + (kq * 128) * 24 + rq * 6;
#pragma unroll 4
        for (int k = 0; k < 128; ++k) {
            float4 hv = *reinterpret_cast<const float4*>(hp);
            const float2* wq = reinterpret_cast<const float2*>(wp);
            float2 w01 = wq[0], w23 = wq[1], w45 = wq[2];
            float w[6] = {w01.x, w01.y, w23.x, w23.y, w45.x, w45.y};
#pragma unroll
            for (int rr = 0; rr < 6; ++rr) {
                acc[rr][0] += w[rr] * hv.x;
                acc[rr][1] += w[rr] * hv.y;
                acc[rr][2] += w[rr] * hv.z;
                acc[rr][3] += w[rr] * hv.w;
            }
            hp += 68; wp += 24;
        }
#pragma unroll
        for (int rr = 0; rr < 6; ++rr)
#pragma unroll
            for (int bi = 0; bi < 4; ++bi)
                Pm[((rq * 6 + rr) * 64 + (bq * 4 + bi)) * 4 + kq] = acc[rr][bi];
        __syncthreads();

        // --- phase B: reduce partials, gates, write h_new + outputs ---
        float* __restrict__ hdst = g_h[p ^ 1][d];
        {
            float4 q;
            q = *(const float4*)&Pm[((pj0) * 64 + pb) * 4];
            float zr0 = q.x + q.y + q.z + q.w + bh_r0;
            q = *(const float4*)&Pm[((8 + pj0) * 64 + pb) * 4];
            float zz0 = q.x + q.y + q.z + q.w + bh_z0;
            q = *(const float4*)&Pm[((16 + pj0) * 64 + pb) * 4];
            float zn0 = q.x + q.y + q.z + q.w + bh_n0;
            q = *(const float4*)&Pm[((pj0 + 1) * 64 + pb) * 4];
            float zr1 = q.x + q.y + q.z + q.w + bh_r1;
            q = *(const float4*)&Pm[((8 + pj0 + 1) * 64 + pb) * 4];
            float zz1 = q.x + q.y + q.z + q.w + bh_z1;
            q = *(const float4*)&Pm[((16 + pj0 + 1) * 64 + pb) * 4];
            float zn1 = q.x + q.y + q.z + q.w + bh_n1;

            float r0 = 1.f / (1.f + __expf(-(air0 + zr0)));
            float z0 = 1.f / (1.f + __expf(-(aiz0 + zz0)));
            float n0 = tanhf(ain0 + r0 * zn0);
            float hp0 = hs[(j0 + pj0) * 68 + pb];
            float hn0 = (1.f - z0) * n0 + z0 * hp0;

            float r1 = 1.f / (1.f + __expf(-(air1 + zr1)));
            float z1 = 1.f / (1.f + __expf(-(aiz1 + zz1)));
            float n1 = tanhf(ain1 + r1 * zn1);
            float hp1 = hs[(j0 + pj0 + 1) * 68 + pb];
            float hn1 = (1.f - z1) * n1 + z1 * hp1;

            hdst[pb * HH + j0 + pj0]     = hn0;
            hdst[pb * HH + j0 + pj0 + 1] = hn1;

            size_t ob = (size_t)(pb * TT + t) * 1024 + d * 512 + j0 + pj0;
            out[ob]     = hn0;
            out[ob + 1] = hn1;
            if (s == TT - 1) {
                size_t hb = HOFF + (size_t)d * BB * HH + pb * HH + j0 + pj0;
                out[hb]     = hn0;
                out[hb + 1] = hn1;
            }
        }
        __threadfence();
        if (s < TT - 1) grid_barrier(s + 1);
    }

    // --- reset barrier counters for next graph replay (safe: see spin rule) ---
    if (tid == 0) {
        for (int i = bid; i < 512; i += NBLK) g_cnt[i] = 0u;
    }
}

// =================================================================
extern "C" void kernel_launch(void* const* d_in, const int* in_sizes, int n_in,
                              void* d_out, int out_size)
{
    const float* x       = (const float*)d_in[0];
    const float* w_ih_fw = (const float*)d_in[1];
    const float* w_hh_fw = (const float*)d_in[2];
    const float* b_ih_fw = (const float*)d_in[3];
    const float* b_hh_fw = (const float*)d_in[4];
    const float* w_ih_bw = (const float*)d_in[5];
    const float* w_hh_bw = (const float*)d_in[6];
    const float* b_ih_bw = (const float*)d_in[7];
    const float* b_hh_bw = (const float*)d_in[8];
    float* out = (float*)d_out;

    cudaFuncSetAttribute(rnn_kernel, cudaFuncAttributeMaxDynamicSharedMemorySize,
                         RNN_SMEM_BYTES);

    dim3 ggrid(G3 / 128, (BB * TT) / 128, 2);
    gemm_zi_kernel<<<ggrid, 256>>>(x, w_ih_fw, b_ih_fw, w_ih_bw, b_ih_bw);
    rnn_kernel<<<NBLK, 256, RNN_SMEM_BYTES>>>(w_hh_fw, w_hh_bw, b_hh_fw, b_hh_bw, out);
}

// round 3
// speedup vs baseline: 2.0032x; 2.0032x over previous
#include <cuda_runtime.h>
#include <cuda_bf16.h>

#define BB 64
#define TT 512
#define DD 512
#define HH 512
#define G3 1536
#define NBLK 128

// ---------------- device scratch (no allocations allowed) ----------------
__device__ float    g_zi[2][TT][BB][G3];       // [dir][t][b][3H] pre-activations
__device__ unsigned g_hhi[2][2][BB * 256];     // [ping][dir][b*256 + k/2] bf16x2 hi
__device__ unsigned g_hlo[2][2][BB * 256];     // [ping][dir][b*256 + k/2] bf16x2 lo
__device__ unsigned g_cnt[512];                // grid barrier counters (zero-init)

// =================================================================
// helpers
// =================================================================
__device__ __forceinline__ unsigned pack2(float a, float b) {
    __nv_bfloat162 t = __floats2bfloat162_rn(a, b);
    return reinterpret_cast<unsigned&>(t);
}
__device__ __forceinline__ void split2(float a, float b, unsigned& hi, unsigned& lo) {
    __nv_bfloat16 ha = __float2bfloat16_rn(a), hb = __float2bfloat16_rn(b);
    __nv_bfloat162 th = __halves2bfloat162(ha, hb);
    hi = reinterpret_cast<unsigned&>(th);
    lo = pack2(a - __bfloat162float(ha), b - __bfloat162float(hb));
}
__device__ __forceinline__ float lo16f(unsigned u) {
    __nv_bfloat162 t = reinterpret_cast<__nv_bfloat162&>(u);
    return __bfloat162float(t.x);
}
__device__ __forceinline__ float hi16f(unsigned u) {
    __nv_bfloat162 t = reinterpret_cast<__nv_bfloat162&>(u);
    return __bfloat162float(t.y);
}
__device__ __forceinline__ void mma16816(float* c, const unsigned* a, const unsigned* b) {
    asm volatile(
        "mma.sync.aligned.m16n8k16.row.col.f32.bf16.bf16.f32 "
        "{%0,%1,%2,%3}, {%4,%5,%6,%7}, {%8,%9}, {%0,%1,%2,%3};"
        : "+f"(c[0]), "+f"(c[1]), "+f"(c[2]), "+f"(c[3])
        : "r"(a[0]), "r"(a[1]), "r"(a[2]), "r"(a[3]), "r"(b[0]), "r"(b[1]));
}

// =================================================================
// Kernel 1: zi = x @ W_ih^T + b_ih   (fp32 SGEMM, unchanged from R2)
// =================================================================
__global__ void __launch_bounds__(256, 2) gemm_zi_kernel(
    const float* __restrict__ x,
    const float* __restrict__ w_fw, const float* __restrict__ b_fw,
    const float* __restrict__ w_bw, const float* __restrict__ b_bw)
{
    const int d = blockIdx.z;
    const float* __restrict__ W  = d ? w_bw : w_fw;
    const float* __restrict__ Bi = d ? b_bw : b_fw;
    float* __restrict__ zi = &g_zi[d][0][0][0];

    __shared__ float As[16][132];
    __shared__ float Bs[16][132];

    const int m0 = blockIdx.y * 128;
    const int n0 = blockIdx.x * 128;
    const int tid = threadIdx.x;
    const int tx = tid & 15;
    const int ty = tid >> 4;

    float acc[8][8];
#pragma unroll
    for (int i = 0; i < 8; i++)
#pragma unroll
        for (int j = 0; j < 8; j++) acc[i][j] = 0.f;

    for (int kt = 0; kt < DD; kt += 16) {
#pragma unroll
        for (int i = 0; i < 2; i++) {
            int l = tid * 2 + i;
            int row = l >> 2, kf = l & 3;
            float4 av = *reinterpret_cast<const float4*>(
                x + (size_t)(m0 + row) * DD + kt + kf * 4);
            As[kf * 4 + 0][row] = av.x; As[kf * 4 + 1][row] = av.y;
            As[kf * 4 + 2][row] = av.z; As[kf * 4 + 3][row] = av.w;
            float4 bv = *reinterpret_cast<const float4*>(
                W + (size_t)(n0 + row) * DD + kt + kf * 4);
            Bs[kf * 4 + 0][row] = bv.x; Bs[kf * 4 + 1][row] = bv.y;
            Bs[kf * 4 + 2][row] = bv.z; Bs[kf * 4 + 3][row] = bv.w;
        }
        __syncthreads();
#pragma unroll
        for (int k = 0; k < 16; k++) {
            float a[8], bb[8];
            *(float4*)&a[0]  = *(const float4*)&As[k][ty * 8];
            *(float4*)&a[4]  = *(const float4*)&As[k][ty * 8 + 4];
            *(float4*)&bb[0] = *(const float4*)&Bs[k][tx * 8];
            *(float4*)&bb[4] = *(const float4*)&Bs[k][tx * 8 + 4];
#pragma unroll
            for (int i = 0; i < 8; i++)
#pragma unroll
                for (int j = 0; j < 8; j++)
                    acc[i][j] += a[i] * bb[j];
        }
        __syncthreads();
    }

    float bias[8];
#pragma unroll
    for (int j = 0; j < 8; j++) bias[j] = Bi[n0 + tx * 8 + j];

#pragma unroll
    for (int i = 0; i < 8; i++) {
        int m = m0 + ty * 8 + i;
        int t = m & (TT - 1);
        int b = m >> 9;
        float* dst = zi + (size_t)(t * BB + b) * G3 + n0 + tx * 8;
        float4 v0, v1;
        v0.x = acc[i][0] + bias[0]; v0.y = acc[i][1] + bias[1];
        v0.z = acc[i][2] + bias[2]; v0.w = acc[i][3] + bias[3];
        v1.x = acc[i][4] + bias[4]; v1.y = acc[i][5] + bias[5];
        v1.z = acc[i][6] + bias[6]; v1.w = acc[i][7] + bias[7];
        *reinterpret_cast<float4*>(dst)     = v0;
        *reinterpret_cast<float4*>(dst + 4) = v1;
    }
}

// =================================================================
// Kernel 2: persistent recurrence with bf16 hi/lo split MMA.
// 128 blocks = 2 dirs x 64 j-slices(8).  M=32 (24 real rows), N=64, K=512.
// W_hh fragments live in REGISTERS (k-split across 8 warps).
// =================================================================
#define HS_STRIDE 260                   // words per batch row (conflict-free frags)
#define PM_STRIDE 65
#define SM_HS (64 * HS_STRIDE)          // 16640 words per matrix
#define SM_PM (8 * 32 * PM_STRIDE)      // 16640 floats
#define RNN_SMEM_BYTES ((SM_HS * 2 + SM_PM) * 4)

__device__ __forceinline__ void grid_barrier(int idx)
{
    __syncthreads();
    if (threadIdx.x == 0) {
        __threadfence();
        atomicAdd(&g_cnt[idx], 1u);
        unsigned v;
        do {
            v = *((volatile unsigned*)&g_cnt[idx]);
        } while (v != 0u && v < (unsigned)NBLK);
        __threadfence();
    }
    __syncthreads();
}

__global__ void __launch_bounds__(256, 1) rnn_kernel(
    const float* __restrict__ whh_fw, const float* __restrict__ whh_bw,
    const float* __restrict__ bhh_fw, const float* __restrict__ bhh_bw,
    float* __restrict__ out)
{
    extern __shared__ unsigned smem_u[];
    unsigned* HsHi = smem_u;                       // [b][k/2] stride 260
    unsigned* HsLo = HsHi + SM_HS;
    float*    Pm   = (float*)(HsLo + SM_HS);       // [warp][row][n] stride 65

    const int bid = blockIdx.x;
    const int d   = bid >> 6;
    const int j0  = (bid & 63) * 8;
    const float* __restrict__ W  = d ? whh_bw : whh_fw;
    const float* __restrict__ Bh = d ? bhh_bw : bhh_fw;

    const int tid  = threadIdx.x;
    const int kw   = tid >> 5;          // warp id = k-split segment (64 k each)
    const int lane = tid & 31;
    const int g    = lane >> 2;
    const int tg   = lane & 3;

    // --- load W_hh fragments into registers (persist all 512 steps) ---
    // rows r: 0..7 gate r, 8..15 gate z, 16..23 gate n, 24..31 pad(0)
    unsigned Ahi[2][4][4], Alo[2][4][4];
#pragma unroll
    for (int mf = 0; mf < 2; mf++)
#pragma unroll
        for (int kt = 0; kt < 4; kt++) {
            const int kc = kw * 64 + kt * 16 + tg * 2;
            const int r0 = mf * 16 + g;
            const int r1 = r0 + 8;
            // row r0 (always real: r0 <= 23)
            {
                const float* wr = W + (size_t)(((r0 >> 3) << 9) + j0 + (r0 & 7)) * HH;
                split2(wr[kc],     wr[kc + 1], Ahi[mf][kt][0], Alo[mf][kt][0]);
                split2(wr[kc + 8], wr[kc + 9], Ahi[mf][kt][2], Alo[mf][kt][2]);
            }
            if (r1 < 24) {
                const float* wr = W + (size_t)(((r1 >> 3) << 9) + j0 + (r1 & 7)) * HH;
                split2(wr[kc],     wr[kc + 1], Ahi[mf][kt][1], Alo[mf][kt][1]);
                split2(wr[kc + 8], wr[kc + 9], Ahi[mf][kt][3], Alo[mf][kt][3]);
            } else {
                Ahi[mf][kt][1] = 0u; Alo[mf][kt][1] = 0u;
                Ahi[mf][kt][3] = 0u; Alo[mf][kt][3] = 0u;
            }
        }

    // --- pointwise mapping: thread owns (batch pb, j0+pj, j0+pj+1), pj even ---
    const int pb = tid >> 2;
    const int pj = (tid * 2) & 7;
    const float bh_r0 = Bh[j0 + pj],         bh_r1 = Bh[j0 + pj + 1];
    const float bh_z0 = Bh[512 + j0 + pj],   bh_z1 = Bh[512 + j0 + pj + 1];
    const float bh_n0 = Bh[1024 + j0 + pj],  bh_n1 = Bh[1024 + j0 + pj + 1];
    const int   wsel  = (j0 + pj) >> 1;      // packed word index for this j pair

    // --- zero h ping buffer 0 (this block's j-slice, all batches) ---
    for (int i = tid; i < 256; i += 256) {
        int b = i >> 2, w = (j0 >> 1) + (i & 3);
        g_hhi[0][d][b * 256 + w] = 0u;
        g_hlo[0][d][b * 256 + w] = 0u;
    }
    __threadfence();
    grid_barrier(0);

    const size_t HOFF = (size_t)BB * TT * 1024;

    for (int s = 0; s < TT; ++s) {
        const int p = s & 1;
        const int t = d ? (TT - 1 - s) : s;

        // prefetch zi pre-activations for this thread's 2 outputs
        const float* __restrict__ zib = &g_zi[d][t][pb][0];
        const float2 air = *(const float2*)&zib[j0 + pj];
        const float2 aiz = *(const float2*)&zib[512 + j0 + pj];
        const float2 ain = *(const float2*)&zib[1024 + j0 + pj];

        // --- stage packed h (hi/lo) from global into SMEM (copy only) ---
        {
            const uint4* __restrict__ sh = (const uint4*)g_hhi[p][d];
            const uint4* __restrict__ sl = (const uint4*)g_hlo[p][d];
#pragma unroll
            for (int i = 0; i < 16; ++i) {
                int idx = i * 256 + tid;            // uint4 index over 64*64
                int b = idx >> 6, w4 = idx & 63;
                uint4 vh = __ldcg(sh + idx);
                uint4 vl = __ldcg(sl + idx);
                *(uint4*)&HsHi[b * HS_STRIDE + w4 * 4] = vh;
                *(uint4*)&HsLo[b * HS_STRIDE + w4 * 4] = vl;
            }
        }
        __syncthreads();

        // --- MMA phase: acc[mf][nf][4] over this warp's 64-k segment ---
        float acc[2][8][4];
#pragma unroll
        for (int mf = 0; mf < 2; mf++)
#pragma unroll
            for (int nf = 0; nf < 8; nf++)
#pragma unroll
                for (int i = 0; i < 4; i++) acc[mf][nf][i] = 0.f;

#pragma unroll
        for (int kt = 0; kt < 4; kt++) {
            const int k0h = (kw * 64 + kt * 16) >> 1;
#pragma unroll
            for (int nf = 0; nf < 8; nf++) {
                const int b = nf * 8 + g;
                unsigned bh[2], bl[2];
                bh[0] = HsHi[b * HS_STRIDE + k0h + tg];
                bh[1] = HsHi[b * HS_STRIDE + k0h + 4 + tg];
                bl[0] = HsLo[b * HS_STRIDE + k0h + tg];
                bl[1] = HsLo[b * HS_STRIDE + k0h + 4 + tg];
                mma16816(acc[0][nf], Ahi[0][kt], bh);
                mma16816(acc[0][nf], Ahi[0][kt], bl);
                mma16816(acc[0][nf], Alo[0][kt], bh);
                mma16816(acc[1][nf], Ahi[1][kt], bh);
                mma16816(acc[1][nf], Ahi[1][kt], bl);
                mma16816(acc[1][nf], Alo[1][kt], bh);
            }
        }

        // --- store partials: Pm[warp][row][n] ---
        {
            float* pw = Pm + kw * (32 * PM_STRIDE);
#pragma unroll
            for (int mf = 0; mf < 2; mf++)
#pragma unroll
                for (int nf = 0; nf < 8; nf++) {
                    const int c = nf * 8 + tg * 2;
                    const int r0 = mf * 16 + g;
                    pw[r0 * PM_STRIDE + c]     = acc[mf][nf][0];
                    pw[r0 * PM_STRIDE + c + 1] = acc[mf][nf][1];
                    if (mf == 0) {                    // rows 8..15 (z gate)
                        pw[(r0 + 8) * PM_STRIDE + c]     = acc[mf][nf][2];
                        pw[(r0 + 8) * PM_STRIDE + c + 1] = acc[mf][nf][3];
                    }
                }
        }
        __syncthreads();

        // --- reduce across 8 warps + gates + writes ---
        {
            float zr0 = bh_r0, zr1 = bh_r1, zz0 = bh_z0, zz1 = bh_z1;
            float zn0 = bh_n0, zn1 = bh_n1;
#pragma unroll
            for (int w = 0; w < 8; w++) {
                const float* pw = Pm + w * (32 * PM_STRIDE);
                zr0 += pw[pj * PM_STRIDE + pb];
                zr1 += pw[(pj + 1) * PM_STRIDE + pb];
                zz0 += pw[(8 + pj) * PM_STRIDE + pb];
                zz1 += pw[(9 + pj) * PM_STRIDE + pb];
                zn0 += pw[(16 + pj) * PM_STRIDE + pb];
                zn1 += pw[(17 + pj) * PM_STRIDE + pb];
            }

            // previous h for the z-blend (hi+lo reconstruction, err ~4e-6)
            unsigned uh = HsHi[pb * HS_STRIDE + wsel];
            unsigned ul = HsLo[pb * HS_STRIDE + wsel];
            float hp0 = lo16f(uh) + lo16f(ul);
            float hp1 = hi16f(uh) + hi16f(ul);

            float r0 = 1.f / (1.f + __expf(-(air.x + zr0)));
            float z0 = 1.f / (1.f + __expf(-(aiz.x + zz0)));
            float n0 = tanhf(ain.x + r0 * zn0);
            float hn0 = (1.f - z0) * n0 + z0 * hp0;

            float r1 = 1.f / (1.f + __expf(-(air.y + zr1)));
            float z1 = 1.f / (1.f + __expf(-(aiz.y + zz1)));
            float n1 = tanhf(ain.y + r1 * zn1);
            float hn1 = (1.f - z1) * n1 + z1 * hp1;

            unsigned whi, wlo;
            split2(hn0, hn1, whi, wlo);
            g_hhi[p ^ 1][d][pb * 256 + wsel] = whi;
            g_hlo[p ^ 1][d][pb * 256 + wsel] = wlo;

            float2 ov; ov.x = hn0; ov.y = hn1;
            *(float2*)&out[(size_t)(pb * TT + t) * 1024 + d * 512 + j0 + pj] = ov;
            if (s == TT - 1) {
                *(float2*)&out[HOFF + (size_t)d * BB * HH + pb * HH + j0 + pj] = ov;
            }
        }
        __threadfence();
        if (s < TT - 1) grid_barrier(s + 1);
    }

    // --- reset barrier counters for next graph replay ---
    if (tid == 0) {
        for (int i = bid; i < 512; i += NBLK) g_cnt[i] = 0u;
    }
}

// =================================================================
extern "C" void kernel_launch(void* const* d_in, const int* in_sizes, int n_in,
                              void* d_out, int out_size)
{
    const float* x       = (const float*)d_in[0];
    const float* w_ih_fw = (const float*)d_in[1];
    const float* w_hh_fw = (const float*)d_in[2];
    const float* b_ih_fw = (const float*)d_in[3];
    const float* b_hh_fw = (const float*)d_in[4];
    const float* w_ih_bw = (const float*)d_in[5];
    const float* w_hh_bw = (const float*)d_in[6];
    const float* b_ih_bw = (const float*)d_in[7];
    const float* b_hh_bw = (const float*)d_in[8];
    float* out = (float*)d_out;

    cudaFuncSetAttribute(rnn_kernel, cudaFuncAttributeMaxDynamicSharedMemorySize,
                         RNN_SMEM_BYTES);

    dim3 ggrid(G3 / 128, (BB * TT) / 128, 2);
    gemm_zi_kernel<<<ggrid, 256>>>(x, w_ih_fw, b_ih_fw, w_ih_bw, b_ih_bw);
    rnn_kernel<<<NBLK, 256, RNN_SMEM_BYTES>>>(w_hh_fw, w_hh_bw, b_hh_fw, b_hh_bw, out);
}

// round 4
// speedup vs baseline: 2.5472x; 1.2716x over previous
#include <cuda_runtime.h>
#include <cuda_bf16.h>

#define BB 64
#define TT 512
#define DD 512
#define HH 512
#define G3 1536
#define NBLK 128

#define MTOT (BB * TT)            // 32768
#define KW   (DD / 2)             // 256 packed words per row
#define XWRD (MTOT * KW)          // 8388608 words
#define WWRD (G3 * KW)            // 393216 words per dir

// ---------------- device scratch (no allocations allowed) ----------------
__device__ float    g_zi[2][TT][BB][G3];       // [dir][t][b][3H] pre-activations
__device__ unsigned g_xhi[XWRD];               // x split hi (bf16x2 words)
__device__ unsigned g_xlo[XWRD];
__device__ unsigned g_whi[2][WWRD];            // W_ih split
__device__ unsigned g_wlo[2][WWRD];
__device__ unsigned g_hhi[2][2][BB * 256];     // [ping][dir][b*256 + k/2] bf16x2 hi
__device__ unsigned g_hlo[2][2][BB * 256];
__device__ unsigned g_cnt[512];                // grid barrier counters (zero-init)

// =================================================================
// helpers
// =================================================================
__device__ __forceinline__ unsigned pack2(float a, float b) {
    __nv_bfloat162 t = __floats2bfloat162_rn(a, b);
    return reinterpret_cast<unsigned&>(t);
}
__device__ __forceinline__ void split2(float a, float b, unsigned& hi, unsigned& lo) {
    __nv_bfloat16 ha = __float2bfloat16_rn(a), hb = __float2bfloat16_rn(b);
    __nv_bfloat162 th = __halves2bfloat162(ha, hb);
    hi = reinterpret_cast<unsigned&>(th);
    lo = pack2(a - __bfloat162float(ha), b - __bfloat162float(hb));
}
__device__ __forceinline__ float lo16f(unsigned u) {
    __nv_bfloat162 t = reinterpret_cast<__nv_bfloat162&>(u);
    return __bfloat162float(t.x);
}
__device__ __forceinline__ float hi16f(unsigned u) {
    __nv_bfloat162 t = reinterpret_cast<__nv_bfloat162&>(u);
    return __bfloat162float(t.y);
}
__device__ __forceinline__ void mma16816(float* c, const unsigned* a, const unsigned* b) {
    asm volatile(
        "mma.sync.aligned.m16n8k16.row.col.f32.bf16.bf16.f32 "
        "{%0,%1,%2,%3}, {%4,%5,%6,%7}, {%8,%9}, {%0,%1,%2,%3};"
        : "+f"(c[0]), "+f"(c[1]), "+f"(c[2]), "+f"(c[3])
        : "r"(a[0]), "r"(a[1]), "r"(a[2]), "r"(a[3]), "r"(b[0]), "r"(b[1]));
}
__device__ __forceinline__ void cp_async16(unsigned smem_addr, const void* gptr) {
    asm volatile("cp.async.cg.shared.global [%0], [%1], 16;\n"
                 :: "r"(smem_addr), "l"(gptr));
}

// =================================================================
// Kernel 0: split x and W_ih into bf16 hi/lo packed arrays
// =================================================================
__global__ void convert_kernel(const float* __restrict__ x,
                               const float* __restrict__ w_fw,
                               const float* __restrict__ w_bw)
{
    const unsigned idx = blockIdx.x * 256 + threadIdx.x;
    if (idx < XWRD) {
        float2 v = reinterpret_cast<const float2*>(x)[idx];
        split2(v.x, v.y, g_xhi[idx], g_xlo[idx]);
    } else {
        unsigned w = idx - XWRD;
        if (w < 2u * WWRD) {
            int d = w >= WWRD;
            unsigned o = d ? w - WWRD : w;
            const float* src = d ? w_bw : w_fw;
            float2 v = reinterpret_cast<const float2*>(src)[o];
            split2(v.x, v.y, g_whi[d][o], g_wlo[d][o]);
        }
    }
}

// =================================================================
// Kernel 1: zi = x @ W_ih^T + b_ih  via split-bf16 MMA.
// 128x128 tile, K-chunk 32, cp.async 2-stage, 8 warps of 64x32.
// =================================================================
#define GS_ROWW 20                  // words per row per 32-k chunk (16 data + 4 pad)
#define GS_MAT  (128 * GS_ROWW)     // 2560 words per matrix per stage
#define GEMM_SMEM_BYTES (8 * GS_MAT * 4)   // AH0 AH1 AL0 AL1 BH0 BH1 BL0 BL1

__global__ void __launch_bounds__(256, 1) gemm_zi_kernel(
    const float* __restrict__ b_fw, const float* __restrict__ b_bw)
{
    extern __shared__ unsigned gsm[];
    // region bases (words): AH=0, AL=5120, BH=10240, BL=15360; +stage*2560
    const int d = blockIdx.z;
    const float* __restrict__ Bi = d ? b_bw : b_fw;
    const unsigned* __restrict__ wh = g_whi[d];
    const unsigned* __restrict__ wl = g_wlo[d];
    float* __restrict__ zi = &g_zi[d][0][0][0];

    const int m0 = blockIdx.y * 128;
    const int n0 = blockIdx.x * 128;
    const int tid  = threadIdx.x;
    const int warp = tid >> 5;
    const int lane = tid & 31;
    const int g    = lane >> 2;
    const int tg   = lane & 3;
    const int wm   = warp >> 2;       // 0..1 -> m offset *64
    const int wn   = warp & 3;        // 0..3 -> n offset *32

    const unsigned smem_base = (unsigned)__cvta_generic_to_shared(gsm);

    // loader mapping: 8 chunks of 16B per thread per k-iter
    //   id = i*256+tid; mat=id>>9 (0:AH 1:AL 2:BH 3:BL); r=(id&511)>>2; c=id&3
    auto load_stage = [&](int kt, int s) {
#pragma unroll
        for (int i = 0; i < 8; i++) {
            int id  = i * 256 + tid;
            int mat = id >> 9;
            int rem = id & 511;
            int r   = rem >> 2;
            int c   = rem & 3;
            const unsigned* src;
            if (mat == 0)      src = g_xhi + (size_t)(m0 + r) * KW;
            else if (mat == 1) src = g_xlo + (size_t)(m0 + r) * KW;
            else if (mat == 2) src = wh    + (size_t)(n0 + r) * KW;
            else               src = wl    + (size_t)(n0 + r) * KW;
            src += kt * 16 + c * 4;
            unsigned dst = smem_base +
                (mat * 2 * GS_MAT + s * GS_MAT + r * GS_ROWW + c * 4) * 4;
            cp_async16(dst, src);
        }
        asm volatile("cp.async.commit_group;\n");
    };

    float acc[4][4][4];
#pragma unroll
    for (int mi = 0; mi < 4; mi++)
#pragma unroll
        for (int ni = 0; ni < 4; ni++)
#pragma unroll
            for (int i = 0; i < 4; i++) acc[mi][ni][i] = 0.f;

    load_stage(0, 0);

    for (int kt = 0; kt < 16; ++kt) {
        if (kt + 1 < 16) {
            load_stage(kt + 1, (kt + 1) & 1);
            asm volatile("cp.async.wait_group 1;\n");
        } else {
            asm volatile("cp.async.wait_group 0;\n");
        }
        __syncthreads();

        const int s = kt & 1;
        const unsigned* AH = gsm + 0 * 2 * GS_MAT + s * GS_MAT;
        const unsigned* AL = gsm + 1 * 2 * GS_MAT + s * GS_MAT;
        const unsigned* BH = gsm + 2 * 2 * GS_MAT + s * GS_MAT;
        const unsigned* BL = gsm + 3 * 2 * GS_MAT + s * GS_MAT;

#pragma unroll
        for (int kk = 0; kk < 2; ++kk) {
            unsigned ah[4][4], al[4][4], bh[4][2], bl[4][2];
#pragma unroll
            for (int mi = 0; mi < 4; mi++) {
                const int row = wm * 64 + mi * 16 + g;
                const int b0 = row * GS_ROWW + kk * 8 + tg;
                const int b1 = b0 + 8 * GS_ROWW;
                ah[mi][0] = AH[b0];     ah[mi][1] = AH[b1];
                ah[mi][2] = AH[b0 + 4]; ah[mi][3] = AH[b1 + 4];
                al[mi][0] = AL[b0];     al[mi][1] = AL[b1];
                al[mi][2] = AL[b0 + 4]; al[mi][3] = AL[b1 + 4];
            }
#pragma unroll
            for (int ni = 0; ni < 4; ni++) {
                const int n = wn * 32 + ni * 8 + g;
                const int b0 = n * GS_ROWW + kk * 8 + tg;
                bh[ni][0] = BH[b0]; bh[ni][1] = BH[b0 + 4];
                bl[ni][0] = BL[b0]; bl[ni][1] = BL[b0 + 4];
            }
#pragma unroll
            for (int mi = 0; mi < 4; mi++)
#pragma unroll
                for (int ni = 0; ni < 4; ni++) {
                    mma16816(acc[mi][ni], ah[mi], bh[ni]);
                    mma16816(acc[mi][ni], ah[mi], bl[ni]);
                    mma16816(acc[mi][ni], al[mi], bh[ni]);
                }
        }
        __syncthreads();
    }

    // --- epilogue: +bias, write zi permuted [t][b][g] ---
    float bias[4][2];
#pragma unroll
    for (int ni = 0; ni < 4; ni++) {
        const int n = n0 + wn * 32 + ni * 8 + tg * 2;
        bias[ni][0] = Bi[n]; bias[ni][1] = Bi[n + 1];
    }
#pragma unroll
    for (int mi = 0; mi < 4; mi++) {
        const int row0 = m0 + wm * 64 + mi * 16 + g;
        const int row1 = row0 + 8;
        const int t0 = row0 & (TT - 1), b0r = row0 >> 9;
        const int t1 = row1 & (TT - 1), b1r = row1 >> 9;
        float* d0 = zi + (size_t)(t0 * BB + b0r) * G3;
        float* d1 = zi + (size_t)(t1 * BB + b1r) * G3;
#pragma unroll
        for (int ni = 0; ni < 4; ni++) {
            const int n = n0 + wn * 32 + ni * 8 + tg * 2;
            float2 v0, v1;
            v0.x = acc[mi][ni][0] + bias[ni][0];
            v0.y = acc[mi][ni][1] + bias[ni][1];
            v1.x = acc[mi][ni][2] + bias[ni][0];
            v1.y = acc[mi][ni][3] + bias[ni][1];
            *(float2*)(d0 + n) = v0;
            *(float2*)(d1 + n) = v1;
        }
    }
}

// =================================================================
// Kernel 2: persistent recurrence with bf16 hi/lo split MMA (as R3).
// =================================================================
#define HS_STRIDE 260
#define PM_STRIDE 65
#define SM_HS (64 * HS_STRIDE)
#define SM_PM (8 * 32 * PM_STRIDE)
#define RNN_SMEM_BYTES ((SM_HS * 2 + SM_PM) * 4)

__device__ __forceinline__ void grid_barrier(int idx)
{
    __syncthreads();
    if (threadIdx.x == 0) {
        __threadfence();
        atomicAdd(&g_cnt[idx], 1u);
        unsigned v;
        do {
            v = *((volatile unsigned*)&g_cnt[idx]);
        } while (v != 0u && v < (unsigned)NBLK);
        __threadfence();
    }
    __syncthreads();
}

__global__ void __launch_bounds__(256, 1) rnn_kernel(
    const float* __restrict__ whh_fw, const float* __restrict__ whh_bw,
    const float* __restrict__ bhh_fw, const float* __restrict__ bhh_bw,
    float* __restrict__ out)
{
    extern __shared__ unsigned smem_u[];
    unsigned* HsHi = smem_u;
    unsigned* HsLo = HsHi + SM_HS;
    float*    Pm   = (float*)(HsLo + SM_HS);

    const int bid = blockIdx.x;
    const int d   = bid >> 6;
    const int j0  = (bid & 63) * 8;
    const float* __restrict__ W  = d ? whh_bw : whh_fw;
    const float* __restrict__ Bh = d ? bhh_bw : bhh_fw;

    const int tid  = threadIdx.x;
    const int kw   = tid >> 5;
    const int lane = tid & 31;
    const int g    = lane >> 2;
    const int tg   = lane & 3;

    unsigned Ahi[2][4][4], Alo[2][4][4];
#pragma unroll
    for (int mf = 0; mf < 2; mf++)
#pragma unroll
        for (int kt = 0; kt < 4; kt++) {
            const int kc = kw * 64 + kt * 16 + tg * 2;
            const int r0 = mf * 16 + g;
            const int r1 = r0 + 8;
            {
                const float* wr = W + (size_t)(((r0 >> 3) << 9) + j0 + (r0 & 7)) * HH;
                split2(wr[kc],     wr[kc + 1], Ahi[mf][kt][0], Alo[mf][kt][0]);
                split2(wr[kc + 8], wr[kc + 9], Ahi[mf][kt][2], Alo[mf][kt][2]);
            }
            if (r1 < 24) {
                const float* wr = W + (size_t)(((r1 >> 3) << 9) + j0 + (r1 & 7)) * HH;
                split2(wr[kc],     wr[kc + 1], Ahi[mf][kt][1], Alo[mf][kt][1]);
                split2(wr[kc + 8], wr[kc + 9], Ahi[mf][kt][3], Alo[mf][kt][3]);
            } else {
                Ahi[mf][kt][1] = 0u; Alo[mf][kt][1] = 0u;
                Ahi[mf][kt][3] = 0u; Alo[mf][kt][3] = 0u;
            }
        }

    const int pb = tid >> 2;
    const int pj = (tid * 2) & 7;
    const float bh_r0 = Bh[j0 + pj],         bh_r1 = Bh[j0 + pj + 1];
    const float bh_z0 = Bh[512 + j0 + pj],   bh_z1 = Bh[512 + j0 + pj + 1];
    const float bh_n0 = Bh[1024 + j0 + pj],  bh_n1 = Bh[1024 + j0 + pj + 1];
    const int   wsel  = (j0 + pj) >> 1;

    for (int i = tid; i < 256; i += 256) {
        int b = i >> 2, w = (j0 >> 1) + (i & 3);
        g_hhi[0][d][b * 256 + w] = 0u;
        g_hlo[0][d][b * 256 + w] = 0u;
    }
    __threadfence();
    grid_barrier(0);

    const size_t HOFF = (size_t)BB * TT * 1024;

    for (int s = 0; s < TT; ++s) {
        const int p = s & 1;
        const int t = d ? (TT - 1 - s) : s;

        const float* __restrict__ zib = &g_zi[d][t][pb][0];
        const float2 air = *(const float2*)&zib[j0 + pj];
        const float2 aiz = *(const float2*)&zib[512 + j0 + pj];
        const float2 ain = *(const float2*)&zib[1024 + j0 + pj];

        {
            const uint4* __restrict__ sh = (const uint4*)g_hhi[p][d];
            const uint4* __restrict__ sl = (const uint4*)g_hlo[p][d];
#pragma unroll
            for (int i = 0; i < 16; ++i) {
                int idx = i * 256 + tid;
                int b = idx >> 6, w4 = idx & 63;
                uint4 vh = __ldcg(sh + idx);
                uint4 vl = __ldcg(sl + idx);
                *(uint4*)&HsHi[b * HS_STRIDE + w4 * 4] = vh;
                *(uint4*)&HsLo[b * HS_STRIDE + w4 * 4] = vl;
            }
        }
        __syncthreads();

        float acc[2][8][4];
#pragma unroll
        for (int mf = 0; mf < 2; mf++)
#pragma unroll
            for (int nf = 0; nf < 8; nf++)
#pragma unroll
                for (int i = 0; i < 4; i++) acc[mf][nf][i] = 0.f;

#pragma unroll
        for (int kt = 0; kt < 4; kt++) {
            const int k0h = (kw * 64 + kt * 16) >> 1;
#pragma unroll
            for (int nf = 0; nf < 8; nf++) {
                const int b = nf * 8 + g;
                unsigned bh[2], bl[2];
                bh[0] = HsHi[b * HS_STRIDE + k0h + tg];
                bh[1] = HsHi[b * HS_STRIDE + k0h + 4 + tg];
                bl[0] = HsLo[b * HS_STRIDE + k0h + tg];
                bl[1] = HsLo[b * HS_STRIDE + k0h + 4 + tg];
                mma16816(acc[0][nf], Ahi[0][kt], bh);
                mma16816(acc[0][nf], Ahi[0][kt], bl);
                mma16816(acc[0][nf], Alo[0][kt], bh);
                mma16816(acc[1][nf], Ahi[1][kt], bh);
                mma16816(acc[1][nf], Ahi[1][kt], bl);
                mma16816(acc[1][nf], Alo[1][kt], bh);
            }
        }

        {
            float* pw = Pm + kw * (32 * PM_STRIDE);
#pragma unroll
            for (int mf = 0; mf < 2; mf++)
#pragma unroll
                for (int nf = 0; nf < 8; nf++) {
                    const int c = nf * 8 + tg * 2;
                    const int r0 = mf * 16 + g;
                    pw[r0 * PM_STRIDE + c]     = acc[mf][nf][0];
                    pw[r0 * PM_STRIDE + c + 1] = acc[mf][nf][1];
                    if (mf == 0) {
                        pw[(r0 + 8) * PM_STRIDE + c]     = acc[mf][nf][2];
                        pw[(r0 + 8) * PM_STRIDE + c + 1] = acc[mf][nf][3];
                    }
                }
        }
        __syncthreads();

        {
            float zr0 = bh_r0, zr1 = bh_r1, zz0 = bh_z0, zz1 = bh_z1;
            float zn0 = bh_n0, zn1 = bh_n1;
#pragma unroll
            for (int w = 0; w < 8; w++) {
                const float* pw = Pm + w * (32 * PM_STRIDE);
                zr0 += pw[pj * PM_STRIDE + pb];
                zr1 += pw[(pj + 1) * PM_STRIDE + pb];
                zz0 += pw[(8 + pj) * PM_STRIDE + pb];
                zz1 += pw[(9 + pj) * PM_STRIDE + pb];
                zn0 += pw[(16 + pj) * PM_STRIDE + pb];
                zn1 += pw[(17 + pj) * PM_STRIDE + pb];
            }

            unsigned uh = HsHi[pb * HS_STRIDE + wsel];
            unsigned ul = HsLo[pb * HS_STRIDE + wsel];
            float hp0 = lo16f(uh) + lo16f(ul);
            float hp1 = hi16f(uh) + hi16f(ul);

            float r0 = 1.f / (1.f + __expf(-(air.x + zr0)));
            float z0 = 1.f / (1.f + __expf(-(aiz.x + zz0)));
            float n0 = tanhf(ain.x + r0 * zn0);
            float hn0 = (1.f - z0) * n0 + z0 * hp0;

            float r1 = 1.f / (1.f + __expf(-(air.y + zr1)));
            float z1 = 1.f / (1.f + __expf(-(aiz.y + zz1)));
            float n1 = tanhf(ain.y + r1 * zn1);
            float hn1 = (1.f - z1) * n1 + z1 * hp1;

            unsigned whi2, wlo2;
            split2(hn0, hn1, whi2, wlo2);
            g_hhi[p ^ 1][d][pb * 256 + wsel] = whi2;
            g_hlo[p ^ 1][d][pb * 256 + wsel] = wlo2;

            float2 ov; ov.x = hn0; ov.y = hn1;
            *(float2*)&out[(size_t)(pb * TT + t) * 1024 + d * 512 + j0 + pj] = ov;
            if (s == TT - 1) {
                *(float2*)&out[HOFF + (size_t)d * BB * HH + pb * HH + j0 + pj] = ov;
            }
        }
        __threadfence();
        if (s < TT - 1) grid_barrier(s + 1);
    }

    if (tid == 0) {
        for (int i = bid; i < 512; i += NBLK) g_cnt[i] = 0u;
    }
}

// =================================================================
extern "C" void kernel_launch(void* const* d_in, const int* in_sizes, int n_in,
                              void* d_out, int out_size)
{
    const float* x       = (const float*)d_in[0];
    const float* w_hh_fw = (const float*)d_in[2];
    const float* b_ih_fw = (const float*)d_in[3];
    const float* b_hh_fw = (const float*)d_in[4];
    const float* w_ih_fw = (const float*)d_in[1];
    const float* w_ih_bw = (const float*)d_in[5];
    const float* w_hh_bw = (const float*)d_in[6];
    const float* b_ih_bw = (const float*)d_in[7];
    const float* b_hh_bw = (const float*)d_in[8];
    float* out = (float*)d_out;

    cudaFuncSetAttribute(gemm_zi_kernel, cudaFuncAttributeMaxDynamicSharedMemorySize,
                         GEMM_SMEM_BYTES);
    cudaFuncSetAttribute(rnn_kernel, cudaFuncAttributeMaxDynamicSharedMemorySize,
                         RNN_SMEM_BYTES);

    const unsigned total_words = XWRD + 2 * WWRD;
    convert_kernel<<<(total_words + 255) / 256, 256>>>(x, w_ih_fw, w_ih_bw);

    dim3 ggrid(G3 / 128, MTOT / 128, 2);
    gemm_zi_kernel<<<ggrid, 256, GEMM_SMEM_BYTES>>>(b_ih_fw, b_ih_bw);

    rnn_kernel<<<NBLK, 256, RNN_SMEM_BYTES>>>(w_hh_fw, w_hh_bw, b_hh_fw, b_hh_bw, out);
}

// round 5
// speedup vs baseline: 2.6065x; 1.0233x over previous
#include <cuda_runtime.h>
#include <cuda_bf16.h>

#define BB 64
#define TT 512
#define DD 512
#define HH 512
#define G3 1536
#define NBLK 128

#define MTOT (BB * TT)            // 32768
#define KW   (DD / 2)             // 256 packed words per row
#define XWRD (MTOT * KW)
#define WWRD (G3 * KW)

// ---------------- device scratch (no allocations allowed) ----------------
__device__ float    g_zi[2][TT][BB][G3];
__device__ unsigned g_xhi[XWRD];
__device__ unsigned g_xlo[XWRD];
__device__ unsigned g_whi[2][WWRD];
__device__ unsigned g_wlo[2][WWRD];
__device__ unsigned g_hhi[2][2][BB * 256];
__device__ unsigned g_hlo[2][2][BB * 256];
__device__ unsigned g_cnt[512];

// =================================================================
// helpers
// =================================================================
__device__ __forceinline__ unsigned pack2(float a, float b) {
    __nv_bfloat162 t = __floats2bfloat162_rn(a, b);
    return reinterpret_cast<unsigned&>(t);
}
__device__ __forceinline__ void split2(float a, float b, unsigned& hi, unsigned& lo) {
    __nv_bfloat16 ha = __float2bfloat16_rn(a), hb = __float2bfloat16_rn(b);
    __nv_bfloat162 th = __halves2bfloat162(ha, hb);
    hi = reinterpret_cast<unsigned&>(th);
    lo = pack2(a - __bfloat162float(ha), b - __bfloat162float(hb));
}
__device__ __forceinline__ float lo16f(unsigned u) {
    __nv_bfloat162 t = reinterpret_cast<__nv_bfloat162&>(u);
    return __bfloat162float(t.x);
}
__device__ __forceinline__ float hi16f(unsigned u) {
    __nv_bfloat162 t = reinterpret_cast<__nv_bfloat162&>(u);
    return __bfloat162float(t.y);
}
__device__ __forceinline__ void mma16816(float* c, const unsigned* a, const unsigned* b) {
    asm volatile(
        "mma.sync.aligned.m16n8k16.row.col.f32.bf16.bf16.f32 "
        "{%0,%1,%2,%3}, {%4,%5,%6,%7}, {%8,%9}, {%0,%1,%2,%3};"
        : "+f"(c[0]), "+f"(c[1]), "+f"(c[2]), "+f"(c[3])
        : "r"(a[0]), "r"(a[1]), "r"(a[2]), "r"(a[3]), "r"(b[0]), "r"(b[1]));
}
__device__ __forceinline__ void cp_async16(unsigned smem_addr, const void* gptr) {
    asm volatile("cp.async.cg.shared.global [%0], [%1], 16;\n"
                 :: "r"(smem_addr), "l"(gptr));
}
__device__ __forceinline__ void ldsm4(unsigned addr, unsigned* r) {
    asm volatile("ldmatrix.sync.aligned.m8n8.x4.shared.b16 {%0,%1,%2,%3}, [%4];"
        : "=r"(r[0]), "=r"(r[1]), "=r"(r[2]), "=r"(r[3]) : "r"(addr));
}
__device__ __forceinline__ void ldsm2(unsigned addr, unsigned* r) {
    asm volatile("ldmatrix.sync.aligned.m8n8.x2.shared.b16 {%0,%1}, [%2];"
        : "=r"(r[0]), "=r"(r[1]) : "r"(addr));
}

// =================================================================
// Kernel 0: split x and W_ih into bf16 hi/lo packed arrays
// =================================================================
__global__ void convert_kernel(const float* __restrict__ x,
                               const float* __restrict__ w_fw,
                               const float* __restrict__ w_bw)
{
    const unsigned idx = blockIdx.x * 256 + threadIdx.x;
    if (idx < XWRD) {
        float2 v = reinterpret_cast<const float2*>(x)[idx];
        split2(v.x, v.y, g_xhi[idx], g_xlo[idx]);
    } else {
        unsigned w = idx - XWRD;
        if (w < 2u * WWRD) {
            int d = w >= WWRD;
            unsigned o = d ? w - WWRD : w;
            const float* src = d ? w_bw : w_fw;
            float2 v = reinterpret_cast<const float2*>(src)[o];
            split2(v.x, v.y, g_whi[d][o], g_wlo[d][o]);
        }
    }
}

// =================================================================
// Kernel 1: zi = x @ W_ih^T + b_ih  via split-bf16 MMA.
// 128x128 tile, K-chunk 32, 4-stage cp.async, ldmatrix, 1 sync/iter.
// =================================================================
#define GS_ROWW 20
#define GS_MAT  (128 * GS_ROWW)              // 2560 words per matrix per stage
#define GEMM_SMEM_BYTES (16 * GS_MAT * 4)    // 4 matrices x 4 stages = 160KB

__global__ void __launch_bounds__(256, 1) gemm_zi_kernel(
    const float* __restrict__ b_fw, const float* __restrict__ b_bw)
{
    extern __shared__ unsigned gsm[];
    const int d = blockIdx.z;
    const float* __restrict__ Bi = d ? b_bw : b_fw;
    const unsigned* __restrict__ wh = g_whi[d];
    const unsigned* __restrict__ wl = g_wlo[d];
    float* __restrict__ zi = &g_zi[d][0][0][0];

    const int m0 = blockIdx.y * 128;
    const int n0 = blockIdx.x * 128;
    const int tid  = threadIdx.x;
    const int warp = tid >> 5;
    const int lane = tid & 31;
    const int g    = lane >> 2;
    const int tg   = lane & 3;
    const int wm   = warp >> 2;
    const int wn   = warp & 3;

    const unsigned smem_base = (unsigned)__cvta_generic_to_shared(gsm);
    // matrix region bases (words): AH=0, AL=4*GS_MAT, BH=8*GS_MAT, BL=12*GS_MAT

    auto load_stage = [&](int kt, int s) {
#pragma unroll
        for (int i = 0; i < 8; i++) {
            int id  = i * 256 + tid;
            int mat = id >> 9;
            int rem = id & 511;
            int r   = rem >> 2;
            int c   = rem & 3;
            const unsigned* src;
            if (mat == 0)      src = g_xhi + (size_t)(m0 + r) * KW;
            else if (mat == 1) src = g_xlo + (size_t)(m0 + r) * KW;
            else if (mat == 2) src = wh    + (size_t)(n0 + r) * KW;
            else               src = wl    + (size_t)(n0 + r) * KW;
            src += kt * 16 + c * 4;
            unsigned dst = smem_base +
                (mat * 4 * GS_MAT + s * GS_MAT + r * GS_ROWW + c * 4) * 4;
            cp_async16(dst, src);
        }
        asm volatile("cp.async.commit_group;\n");
    };

    float acc[4][4][4];
#pragma unroll
    for (int mi = 0; mi < 4; mi++)
#pragma unroll
        for (int ni = 0; ni < 4; ni++)
#pragma unroll
            for (int i = 0; i < 4; i++) acc[mi][ni][i] = 0.f;

    load_stage(0, 0);
    load_stage(1, 1);
    load_stage(2, 2);

    // ldmatrix lane addressing: row = base + (lane&15), half-word +4 if lane>=16
    const int lr = lane & 15;
    const int lh = (lane >> 4) * 4;

    for (int kt = 0; kt < 16; ++kt) {
        if (kt <= 13)      asm volatile("cp.async.wait_group 2;\n");
        else if (kt == 14) asm volatile("cp.async.wait_group 1;\n");
        else               asm volatile("cp.async.wait_group 0;\n");
        __syncthreads();

        if (kt + 3 < 16) load_stage(kt + 3, (kt + 3) & 3);

        const int st = kt & 3;
        const unsigned baseA_hi = smem_base + (0 * 4 * GS_MAT + st * GS_MAT) * 4;
        const unsigned baseA_lo = smem_base + (1 * 4 * GS_MAT + st * GS_MAT) * 4;
        const unsigned baseB_hi = smem_base + (2 * 4 * GS_MAT + st * GS_MAT) * 4;
        const unsigned baseB_lo = smem_base + (3 * 4 * GS_MAT + st * GS_MAT) * 4;

#pragma unroll
        for (int kk = 0; kk < 2; ++kk) {
            const int kw = kk * 8 + lh;
            unsigned ahi[4][4], alo[4][4], bhi[2][4], blo[2][4];
#pragma unroll
            for (int mi = 0; mi < 4; mi++) {
                unsigned off = ((wm * 64 + mi * 16 + lr) * GS_ROWW + kw) * 4;
                ldsm4(baseA_hi + off, ahi[mi]);
                ldsm4(baseA_lo + off, alo[mi]);
            }
#pragma unroll
            for (int p = 0; p < 2; p++) {
                unsigned off = ((wn * 32 + p * 16 + lr) * GS_ROWW + kw) * 4;
                ldsm4(baseB_hi + off, bhi[p]);
                ldsm4(baseB_lo + off, blo[p]);
            }
#pragma unroll
            for (int mi = 0; mi < 4; mi++)
#pragma unroll
                for (int p = 0; p < 2; p++) {
                    unsigned be[2] = {bhi[p][0], bhi[p][2]};
                    unsigned bo[2] = {bhi[p][1], bhi[p][3]};
                    unsigned le[2] = {blo[p][0], blo[p][2]};
                    unsigned lo_[2] = {blo[p][1], blo[p][3]};
                    mma16816(acc[mi][2 * p],     ahi[mi], be);
                    mma16816(acc[mi][2 * p],     ahi[mi], le);
                    mma16816(acc[mi][2 * p],     alo[mi], be);
                    mma16816(acc[mi][2 * p + 1], ahi[mi], bo);
                    mma16816(acc[mi][2 * p + 1], ahi[mi], lo_);
                    mma16816(acc[mi][2 * p + 1], alo[mi], bo);
                }
        }
    }

    // --- epilogue: +bias, write zi permuted [t][b][g] ---
    float bias[4][2];
#pragma unroll
    for (int ni = 0; ni < 4; ni++) {
        const int n = n0 + wn * 32 + ni * 8 + tg * 2;
        bias[ni][0] = Bi[n]; bias[ni][1] = Bi[n + 1];
    }
#pragma unroll
    for (int mi = 0; mi < 4; mi++) {
        const int row0 = m0 + wm * 64 + mi * 16 + g;
        const int row1 = row0 + 8;
        const int t0 = row0 & (TT - 1), b0r = row0 >> 9;
        const int t1 = row1 & (TT - 1), b1r = row1 >> 9;
        float* d0 = zi + (size_t)(t0 * BB + b0r) * G3;
        float* d1 = zi + (size_t)(t1 * BB + b1r) * G3;
#pragma unroll
        for (int ni = 0; ni < 4; ni++) {
            const int n = n0 + wn * 32 + ni * 8 + tg * 2;
            float2 v0, v1;
            v0.x = acc[mi][ni][0] + bias[ni][0];
            v0.y = acc[mi][ni][1] + bias[ni][1];
            v1.x = acc[mi][ni][2] + bias[ni][0];
            v1.y = acc[mi][ni][3] + bias[ni][1];
            *(float2*)(d0 + n) = v0;
            *(float2*)(d1 + n) = v1;
        }
    }
}

// =================================================================
// Kernel 2: persistent recurrence, re-oriented MMA:
//   A = h (M = 16 batches per warp-SMSP, row-major, ldmatrix)
//   B = W_hh slice (24 rows, SMEM-resident, ldmatrix)
//   k-split 2 (warps 0-3 / 4-7), tiny register-colocated gate math.
// =================================================================
#define WS_STRIDE 260
#define SM_W (24 * WS_STRIDE)        // 6240 words per W matrix
#define SM_H (64 * WS_STRIDE)        // 16640 words per h matrix
#define X_STRIDE 13
#define SM_X (4 * 32 * X_STRIDE)     // 1664 floats
#define RNN_SMEM_BYTES ((2 * SM_W + 2 * SM_H + SM_X) * 4)   // 189,696 B

__device__ __forceinline__ void grid_barrier(int idx)
{
    __syncthreads();
    if (threadIdx.x == 0) {
        __threadfence();
        atomicAdd(&g_cnt[idx], 1u);
        unsigned v;
        do {
            v = *((volatile unsigned*)&g_cnt[idx]);
        } while (v != 0u && v < (unsigned)NBLK);
        __threadfence();
    }
    __syncthreads();
}

__global__ void __launch_bounds__(256, 1) rnn_kernel(
    const float* __restrict__ whh_fw, const float* __restrict__ whh_bw,
    const float* __restrict__ bhh_fw, const float* __restrict__ bhh_bw,
    float* __restrict__ out)
{
    extern __shared__ unsigned su[];
    unsigned* WHi  = su;
    unsigned* WLo  = su + SM_W;
    unsigned* HsHi = su + 2 * SM_W;
    unsigned* HsLo = su + 2 * SM_W + SM_H;
    float*    X    = (float*)(su + 2 * SM_W + 2 * SM_H);

    const int bid = blockIdx.x;
    const int d   = bid >> 6;
    const int j0  = (bid & 63) * 8;
    const float* __restrict__ W  = d ? whh_bw : whh_fw;
    const float* __restrict__ Bh = d ? bhh_bw : bhh_fw;

    const int tid  = threadIdx.x;
    const int warp = tid >> 5;
    const int lane = tid & 31;
    const int mt   = warp & 3;          // m-tile: batches 16mt..16mt+15
    const int kh   = warp >> 2;         // k-half: 0 or 1
    const int g    = lane >> 2;
    const int tg   = lane & 3;

    // --- load W_hh slice split into SMEM (once) ---
    for (int idx = tid; idx < 24 * 256; idx += 256) {
        int r = idx >> 8, kw = idx & 255;
        int grow = ((r >> 3) << 9) + j0 + (r & 7);        // gate*512 + j
        const float* wr = W + (size_t)grow * HH + kw * 2;
        split2(wr[0], wr[1], WHi[r * WS_STRIDE + kw], WLo[r * WS_STRIDE + kw]);
    }

    // --- pointwise constants (warps 0-3 use them) ---
    const int b0i = mt * 16 + g;
    const int b1i = b0i + 8;
    const int jA  = j0 + tg * 2;
    const float2 bh_r = *(const float2*)&Bh[jA];
    const float2 bh_z = *(const float2*)&Bh[512 + jA];
    const float2 bh_n = *(const float2*)&Bh[1024 + jA];
    const int wsel = (j0 >> 1) + tg;

    // --- ldmatrix base addresses ---
    const unsigned sb = (unsigned)__cvta_generic_to_shared(su);
    const unsigned aHiAddr = sb + ((2 * SM_W) + (mt * 16 + (lane & 15)) * WS_STRIDE
                                   + (lane >> 4) * 4) * 4;
    const unsigned aLoAddr = aHiAddr + SM_H * 4;
    const unsigned bRow = ((lane & 7) * WS_STRIDE + ((lane >> 3) & 1) * 4) * 4;
    const unsigned bHiAddr = sb + bRow;
    const unsigned bLoAddr = bHiAddr + SM_W * 4;

    // --- zero h ping buffer 0 (this block's j-slice) ---
    if (tid < 256) {
        int b = tid >> 2, w = (j0 >> 1) + (tid & 3);
        g_hhi[0][d][b * 256 + w] = 0u;
        g_hlo[0][d][b * 256 + w] = 0u;
    }
    __threadfence();
    grid_barrier(0);

    const size_t HOFF = (size_t)BB * TT * 1024;

    for (int s = 0; s < TT; ++s) {
        const int p = s & 1;
        const int t = d ? (TT - 1 - s) : s;

        // prefetch zi pre-activations early (DRAM latency hiding)
        float2 air0, aiz0, ain0, air1, aiz1, ain1;
        if (kh == 0) {
            const float* z0p = &g_zi[d][t][b0i][0];
            const float* z1p = &g_zi[d][t][b1i][0];
            air0 = *(const float2*)&z0p[jA];
            aiz0 = *(const float2*)&z0p[512 + jA];
            ain0 = *(const float2*)&z0p[1024 + jA];
            air1 = *(const float2*)&z1p[jA];
            aiz1 = *(const float2*)&z1p[512 + jA];
            ain1 = *(const float2*)&z1p[1024 + jA];
        }

        // --- stage h via cp.async (L2-only, no transpose) ---
        {
            const unsigned* __restrict__ sh = g_hhi[p][d];
            const unsigned* __restrict__ sl = g_hlo[p][d];
#pragma unroll
            for (int i = 0; i < 16; ++i) {
                int idx = i * 256 + tid;          // 16B-chunk index over 64*64
                int b = idx >> 6, c = idx & 63;
                unsigned dsth = sb + ((2 * SM_W) + b * WS_STRIDE + c * 4) * 4;
                cp_async16(dsth, sh + idx * 4);
                cp_async16(dsth + SM_H * 4, sl + idx * 4);
            }
            asm volatile("cp.async.commit_group;\n");
            asm volatile("cp.async.wait_group 0;\n");
        }
        __syncthreads();

        // --- MMA: acc[nt] = sum over this warp's k-half ---
        float ar[4], az[4], an[4];
#pragma unroll
        for (int i = 0; i < 4; i++) { ar[i] = 0.f; az[i] = 0.f; an[i] = 0.f; }

        const unsigned kbase = (unsigned)(kh * 128) * 4;
#pragma unroll 4
        for (int ks = 0; ks < 16; ++ks) {
            const unsigned koff = kbase + ks * 32;    // (ks*8 words)*4 bytes
            unsigned Af[4], Al[4];
            ldsm4(aHiAddr + koff, Af);
            ldsm4(aLoAddr + koff, Al);
            unsigned Bf[2], Bl[2];
            // nt = 0 (r gate, rows 0-7)
            ldsm2(bHiAddr + koff, Bf);
            ldsm2(bLoAddr + koff, Bl);
            mma16816(ar, Af, Bf); mma16816(ar, Af, Bl); mma16816(ar, Al, Bf);
            // nt = 1 (z gate, rows 8-15)
            ldsm2(bHiAddr + (8 * WS_STRIDE * 4) + koff, Bf);
            ldsm2(bLoAddr + (8 * WS_STRIDE * 4) + koff, Bl);
            mma16816(az, Af, Bf); mma16816(az, Af, Bl); mma16816(az, Al, Bf);
            // nt = 2 (n gate, rows 16-23)
            ldsm2(bHiAddr + (16 * WS_STRIDE * 4) + koff, Bf);
            ldsm2(bLoAddr + (16 * WS_STRIDE * 4) + koff, Bl);
            mma16816(an, Af, Bf); mma16816(an, Af, Bl); mma16816(an, Al, Bf);
        }

        // --- k-reduce: warps 4-7 export, warps 0-3 combine + pointwise ---
        if (kh == 1) {
            float* xp = &X[(mt * 32 + lane) * X_STRIDE];
#pragma unroll
            for (int i = 0; i < 4; i++) {
                xp[i] = ar[i]; xp[4 + i] = az[i]; xp[8 + i] = an[i];
            }
        }
        __syncthreads();

        if (kh == 0) {
            const float* xp = &X[(mt * 32 + lane) * X_STRIDE];
#pragma unroll
            for (int i = 0; i < 4; i++) {
                ar[i] += xp[i]; az[i] += xp[4 + i]; an[i] += xp[8 + i];
            }

            // previous h (hi+lo reconstruction) for the z-blend
            unsigned uh0 = HsHi[b0i * WS_STRIDE + wsel];
            unsigned ul0 = HsLo[b0i * WS_STRIDE + wsel];
            unsigned uh1 = HsHi[b1i * WS_STRIDE + wsel];
            unsigned ul1 = HsLo[b1i * WS_STRIDE + wsel];
            float hp00 = lo16f(uh0) + lo16f(ul0);
            float hp01 = hi16f(uh0) + hi16f(ul0);
            float hp10 = lo16f(uh1) + lo16f(ul1);
            float hp11 = hi16f(uh1) + hi16f(ul1);

            // gates: acc idx 0:(b0,j) 1:(b0,j+1) 2:(b1,j) 3:(b1,j+1)
            float r00 = 1.f / (1.f + __expf(-(air0.x + ar[0] + bh_r.x)));
            float z00 = 1.f / (1.f + __expf(-(aiz0.x + az[0] + bh_z.x)));
            float n00 = tanhf(ain0.x + r00 * (an[0] + bh_n.x));
            float h00 = (1.f - z00) * n00 + z00 * hp00;

            float r01 = 1.f / (1.f + __expf(-(air0.y + ar[1] + bh_r.y)));
            float z01 = 1.f / (1.f + __expf(-(aiz0.y + az[1] + bh_z.y)));
            float n01 = tanhf(ain0.y + r01 * (an[1] + bh_n.y));
            float h01 = (1.f - z01) * n01 + z01 * hp01;

            float r10 = 1.f / (1.f + __expf(-(air1.x + ar[2] + bh_r.x)));
            float z10 = 1.f / (1.f + __expf(-(aiz1.x + az[2] + bh_z.x)));
            float n10 = tanhf(ain1.x + r10 * (an[2] + bh_n.x));
            float h10 = (1.f - z10) * n10 + z10 * hp10;

            float r11 = 1.f / (1.f + __expf(-(air1.y + ar[3] + bh_r.y)));
            float z11 = 1.f / (1.f + __expf(-(aiz1.y + az[3] + bh_z.y)));
            float n11 = tanhf(ain1.y + r11 * (an[3] + bh_n.y));
            float h11 = (1.f - z11) * n11 + z11 * hp11;

            unsigned whi, wlo;
            split2(h00, h01, whi, wlo);
            g_hhi[p ^ 1][d][b0i * 256 + wsel] = whi;
            g_hlo[p ^ 1][d][b0i * 256 + wsel] = wlo;
            split2(h10, h11, whi, wlo);
            g_hhi[p ^ 1][d][b1i * 256 + wsel] = whi;
            g_hlo[p ^ 1][d][b1i * 256 + wsel] = wlo;

            float2 o0; o0.x = h00; o0.y = h01;
            float2 o1; o1.x = h10; o1.y = h11;
            *(float2*)&out[(size_t)(b0i * TT + t) * 1024 + d * 512 + jA] = o0;
            *(float2*)&out[(size_t)(b1i * TT + t) * 1024 + d * 512 + jA] = o1;
            if (s == TT - 1) {
                *(float2*)&out[HOFF + (size_t)d * BB * HH + b0i * HH + jA] = o0;
                *(float2*)&out[HOFF + (size_t)d * BB * HH + b1i * HH + jA] = o1;
            }
        }
        __threadfence();
        if (s < TT - 1) grid_barrier(s + 1);
    }

    if (tid == 0) {
        for (int i = bid; i < 512; i += NBLK) g_cnt[i] = 0u;
    }
}

// =================================================================
extern "C" void kernel_launch(void* const* d_in, const int* in_sizes, int n_in,
                              void* d_out, int out_size)
{
    const float* x       = (const float*)d_in[0];
    const float* w_ih_fw = (const float*)d_in[1];
    const float* w_hh_fw = (const float*)d_in[2];
    const float* b_ih_fw = (const float*)d_in[3];
    const float* b_hh_fw = (const float*)d_in[4];
    const float* w_ih_bw = (const float*)d_in[5];
    const float* w_hh_bw = (const float*)d_in[6];
    const float* b_ih_bw = (const float*)d_in[7];
    const float* b_hh_bw = (const float*)d_in[8];
    float* out = (float*)d_out;

    cudaFuncSetAttribute(gemm_zi_kernel, cudaFuncAttributeMaxDynamicSharedMemorySize,
                         GEMM_SMEM_BYTES);
    cudaFuncSetAttribute(rnn_kernel, cudaFuncAttributeMaxDynamicSharedMemorySize,
                         RNN_SMEM_BYTES);

    const unsigned total_words = XWRD + 2 * WWRD;
    convert_kernel<<<(total_words + 255) / 256, 256>>>(x, w_ih_fw, w_ih_bw);

    dim3 ggrid(G3 / 128, MTOT / 128, 2);
    gemm_zi_kernel<<<ggrid, 256, GEMM_SMEM_BYTES>>>(b_ih_fw, b_ih_bw);

    rnn_kernel<<<NBLK, 256, RNN_SMEM_BYTES>>>(w_hh_fw, w_hh_bw, b_hh_fw, b_hh_bw, out);
}